// round 17
// baseline (speedup 1.0000x reference)
#include <cuda_runtime.h>
#include <stdint.h>

#define NPTS  256
#define DIM   256
#define KNN   16
#define NB2   256       // 1 row per block, 256 threads; 2 CTAs co-resident per SM
#define EPSV  1e-12f
#define CHUNK 32        // dims staged per tile
#define NCH   (DIM / CHUNK)
#define TPAD  36        // tile row stride (floats): conflict-free LDS.128 phases
#define TILEF (NPTS * TPAD)
#define SMEM_DYN (2 * TILEF * 4)   // double-buffered tile, 73728 B

__device__ float    g_part[NB2];
__device__ unsigned g_done = 0;
typedef unsigned long long u64;

#define FMA2(acc, x, y) asm("fma.rn.f32x2 %0, %1, %2, %0;" : "+l"(acc) : "l"(x), "l"(y))
#define ADD2(a, b)      asm("add.rn.f32x2 %0, %0, %1;"     : "+l"(a)   : "l"(b))

__device__ __forceinline__ unsigned warp_min_u32(unsigned v) {
    #pragma unroll
    for (int o = 16; o; o >>= 1) {
        unsigned u = __shfl_xor_sync(0xffffffffu, v, o);
        v = u < v ? u : v;
    }
    return v;
}

__global__ __launch_bounds__(256, 2)
void k_fused(const float* __restrict__ yi, const float* __restrict__ yit,
             float* __restrict__ out) {
    extern __shared__ __align__(16) float dynsmem[];     // 2 tile buffers
    __shared__ __align__(16) float s_n[DIM];             // normalized yi row
    __shared__ __align__(16) float s_t[DIM];             // normalized yit row
    __shared__ unsigned s_cand[NPTS];                    // compacted candidate keys
    __shared__ unsigned s_w3[8];
    __shared__ int      s_cnt;
    __shared__ float    red0[8], red1[8], red2[8];
    __shared__ float4   sh_par;      // ia, ic, rn, rt
    __shared__ float    sh_ds;       // dself
    __shared__ float    shred[8];
    __shared__ unsigned s_last;

    const int t = threadIdx.x, b = blockIdx.x;   // b = row index
    const int w = t >> 5, l = t & 31;

    if (t == 0) s_cnt = 0;           // covered by Phase A's first barrier

    // ---------------- Phase A: normalize row b (3 sums, one reduction) ----------------
    float a = yi [b * DIM + t];
    float c = yit[b * DIM + t];
    float paa = a * a, pcc = c * c, pac = a * c;
    #pragma unroll
    for (int o = 16; o; o >>= 1) {
        paa += __shfl_down_sync(0xffffffffu, paa, o);
        pcc += __shfl_down_sync(0xffffffffu, pcc, o);
        pac += __shfl_down_sync(0xffffffffu, pac, o);
    }
    if (l == 0) { red0[w] = paa; red1[w] = pcc; red2[w] = pac; }
    __syncthreads();
    if (t == 0) {
        float sa = 0.f, sc = 0.f, sac = 0.f;
        #pragma unroll
        for (int m = 0; m < 8; m++) { sa += red0[m]; sc += red1[m]; sac += red2[m]; }
        float ia = 1.0f / sqrtf(sa + EPSV);
        float ic = 1.0f / sqrtf(sc + EPSV);
        float rn = sa * ia * ia, rt = sc * ic * ic;
        sh_par = make_float4(ia, ic, rn, rt);
        sh_ds  = 0.5f * sqrtf(fmaxf(rn + rt - 2.f * ia * ic * sac, 0.f) + EPSV);
    }
    __syncthreads();
    float4 P = sh_par;               // ia, ic, rn, rt of row b
    s_n[t] = a * P.x;
    s_t[t] = c * P.y;
    // (ordered before first compute by the prologue barrier below)

    // ---------------- Phase B: double-buffered staged dual dot, register prefetch ----------------
    const float4* yi4 = (const float4*)yi;
    const ulonglong2* pn = (const ulonglong2*)s_n;
    const ulonglong2* pc = (const ulonglong2*)s_t;

    // staging geometry: 2048 float4/chunk, 8 per thread; slot i: row = i*32+(t>>3), col4 = t&7
    const int rr = t >> 3, kk = t & 7;
    const float4* gbase = yi4 + rr * (DIM / 4) + kk;     // + i*32*(DIM/4) + ch*8
    const int     sbo   = rr * TPAD + 4 * kk;            // + i*32*TPAD
    float* const bufA = dynsmem;
    float* const bufB = dynsmem + TILEF;

    u64 dnx = 0, dny = 0, dtx = 0, dty = 0, ssx = 0, ssy = 0;

    // prologue: stage chunk 0 into bufA
    {
        #pragma unroll
        for (int i = 0; i < 8; i++)
            *(float4*)(bufA + sbo + i * 32 * TPAD) = gbase[i * 32 * (DIM / 4)];
    }
    __syncthreads();

    #pragma unroll
    for (int ch = 0; ch < NCH; ch++) {
        float4 pf0, pf1, pf2, pf3, pf4, pf5, pf6, pf7;
        if (ch + 1 < NCH) {          // issue next chunk's loads early
            const float4* gs = gbase + (ch + 1) * 8;
            pf0 = gs[0 * 32 * (DIM / 4)];  pf1 = gs[1 * 32 * (DIM / 4)];
            pf2 = gs[2 * 32 * (DIM / 4)];  pf3 = gs[3 * 32 * (DIM / 4)];
            pf4 = gs[4 * 32 * (DIM / 4)];  pf5 = gs[5 * 32 * (DIM / 4)];
            pf6 = gs[6 * 32 * (DIM / 4)];  pf7 = gs[7 * 32 * (DIM / 4)];
        }
        const float* cb = (ch & 1) ? bufB : bufA;
        const ulonglong2* tl = (const ulonglong2*)(cb + t * TPAD);
        #pragma unroll
        for (int q = 0; q < 8; q++) {
            ulonglong2 v = tl[q];                 // column t dims, conflict-free
            ulonglong2 A = pn[ch * 8 + q];        // warp-uniform -> LDS broadcast
            ulonglong2 C = pc[ch * 8 + q];
            FMA2(dnx, A.x, v.x);  FMA2(dny, A.y, v.y);
            FMA2(dtx, C.x, v.x);  FMA2(dty, C.y, v.y);
            FMA2(ssx, v.x, v.x);  FMA2(ssy, v.y, v.y);
        }
        if (ch + 1 < NCH) {          // stage next chunk into the other buffer
            float* nb = (ch & 1) ? bufA : bufB;
            *(float4*)(nb + sbo + 0 * 32 * TPAD) = pf0;
            *(float4*)(nb + sbo + 1 * 32 * TPAD) = pf1;
            *(float4*)(nb + sbo + 2 * 32 * TPAD) = pf2;
            *(float4*)(nb + sbo + 3 * 32 * TPAD) = pf3;
            *(float4*)(nb + sbo + 4 * 32 * TPAD) = pf4;
            *(float4*)(nb + sbo + 5 * 32 * TPAD) = pf5;
            *(float4*)(nb + sbo + 6 * 32 * TPAD) = pf6;
            *(float4*)(nb + sbo + 7 * 32 * TPAD) = pf7;
        }
        __syncthreads();             // single barrier per chunk
    }

    ADD2(dnx, dny);  ADD2(dtx, dty);  ADD2(ssx, ssy);
    float nlo, nhi, tlo, thi, slo, shi;
    asm("mov.b64 {%0, %1}, %2;" : "=f"(nlo), "=f"(nhi) : "l"(dnx));
    asm("mov.b64 {%0, %1}, %2;" : "=f"(tlo), "=f"(thi) : "l"(dtx));
    asm("mov.b64 {%0, %1}, %2;" : "=f"(slo), "=f"(shi) : "l"(ssx));

    float ss  = slo + shi;
    float iac = 1.0f / sqrtf(ss + EPSV);
    float rnt = ss * iac * iac;
    float d1  = 0.5f * sqrtf(fmaxf(P.z + rnt - 2.f * ((nlo + nhi) * iac), 0.f) + EPSV);
    float d2  = 0.5f * sqrtf(fmaxf(P.w + rnt - 2.f * ((tlo + thi) * iac), 0.f) + EPSV);

    unsigned key = __float_as_uint(d1);   // positive: bit order == value order

    // ---------------- Pruned exact rank-count selection ----------------
    // T = max over 8 warps of (warp 3rd-smallest key): >=24 keys <= T, so
    // key >= T implies rank >= 23 > KNN. For key < T, rank among candidates
    // equals the exact global rank.
    {
        unsigned kx = key;
        unsigned m1 = warp_min_u32(kx); if (kx == m1) kx = 0xffffffffu;
        unsigned m2 = warp_min_u32(kx); if (kx == m2) kx = 0xffffffffu;
        unsigned m3 = warp_min_u32(kx);
        if (l == 0) s_w3[w] = m3;
    }
    __syncthreads();
    unsigned T = 0;
    #pragma unroll
    for (int m = 0; m < 8; m++) {
        unsigned v = s_w3[m];
        T = v > T ? v : T;
    }

    bool cand = key < T;
    unsigned cmask = __ballot_sync(0xffffffffu, cand);
    int wcnt = __popc(cmask);
    int base = 0;
    if (l == 0 && wcnt) base = atomicAdd(&s_cnt, wcnt);
    base = __shfl_sync(0xffffffffu, base, 0);
    if (cand) s_cand[base + __popc(cmask & ((1u << l) - 1u))] = key;
    __syncthreads();

    int rc = 999;
    if (cand) {
        rc = 0;
        const int n = s_cnt;
        for (int j = 0; j < n; j++) rc += (s_cand[j] < key);
    }

    float contrib = 0.f;
    if (rc >= 1 && rc <= KNN) {
        float df = d1 - d2;
        contrib = df * df;
        if (rc == 1) contrib += fmaxf(sh_ds + 0.6f - d1, 0.f);
    }

    #pragma unroll
    for (int o = 16; o; o >>= 1) contrib += __shfl_down_sync(0xffffffffu, contrib, o);
    if (l == 0) shred[w] = contrib;
    __syncthreads();
    if (t == 0) {
        float s = 0.f;
        #pragma unroll
        for (int m = 0; m < 8; m++) s += shred[m];
        g_part[b] = s - (float)KNN * 0.0025f;    // this row's -K*T
    }

    // ---------------- last arriving block: deterministic final reduce ----------------
    __threadfence();
    __syncthreads();
    if (t == 0) s_last = atomicAdd(&g_done, 1);
    __syncthreads();
    if (s_last == NB2 - 1) {
        float v = *((volatile float*)&g_part[t]);   // 256 partials, 256 threads
        #pragma unroll
        for (int o = 16; o; o >>= 1) v += __shfl_down_sync(0xffffffffu, v, o);
        if (l == 0) shred[w] = v;
        __syncthreads();
        if (t == 0) {
            float s = 0.f;
            #pragma unroll
            for (int m = 0; m < 8; m++) s += shred[m];
            out[0] = s;
            *((volatile unsigned*)&g_done) = 0;     // reset for next graph replay
        }
    }
}

extern "C" void kernel_launch(void* const* d_in, const int* in_sizes, int n_in,
                              void* d_out, int out_size) {
    const float* yi  = (const float*)d_in[0];
    const float* yit = (const float*)d_in[1];
    // host-side attribute set, idempotent, capture-safe
    cudaFuncSetAttribute(k_fused, cudaFuncAttributeMaxDynamicSharedMemorySize, SMEM_DYN);
    k_fused<<<NB2, 256, SMEM_DYN>>>(yi, yit, (float*)d_out);
}